// round 12
// baseline (speedup 1.0000x reference)
#include <cuda_runtime.h>
#include <cuda_fp16.h>
#include <math.h>

typedef unsigned int u32;

#define H 4096
#define IDIM 5632
#define NE 8
#define T 4096
#define NSLOTS (T * 2)
#define BM 128
#define BN 128
#define BK 64
// A: 3 stages x 16KB (fp16 via cp.async); B: 2 bufs x 16KB (fp16, converted in-loop)
#define ASTG 16384
#define BSTG 16384
#define SMEMSZ (1024 + 3 * ASTG + 2 * BSTG)

// ---------------- scratch (device globals; allocation-free) ----------------
__device__ __half g_hx[(size_t)T * H];
__device__ __half g_hact[(size_t)NSLOTS * IDIM];   // silu(g)*u, fp16
__device__ float  g_tmp[(size_t)NSLOTS * IDIM];    // raw gate values fp32
__device__ int    g_counts[NE];
__device__ int    g_offsets[NE];
__device__ int    g_cursor[NE];
__device__ int    g_topi[T * 2];
__device__ float  g_topw[T * 2];
__device__ int    g_tok[NSLOTS];
__device__ float  g_sw[NSLOTS];
__device__ float  g_psum[NE];
__device__ float  g_zsum;

// ---------------- helpers ----------------
__device__ __forceinline__ u32 smem_u32(const void* p) {
    u32 a;
    asm("{ .reg .u64 t; cvta.to.shared.u64 t, %1; cvt.u32.u64 %0, t; }" : "=r"(a) : "l"(p));
    return a;
}
// fp16 tile [128 rows][64 cols], 128B rows = 8 chunks of 16B, full XOR swizzle
__device__ __forceinline__ u32 swoff128(int row, int ch) {
    return (u32)(row * 128 + ((ch ^ (row & 7)) << 4));
}
__device__ __forceinline__ u32 packh(float lo, float hi) {
    u32 r;
    asm("cvt.rn.f16x2.f32 %0, %1, %2;" : "=r"(r) : "f"(hi), "f"(lo));
    return r;
}
// convert 8 fp32 -> 8 fp16 and store one 16B chunk
__device__ __forceinline__ void cvt_sts(u32 addr, float4 a, float4 b) {
    u32 h0 = packh(a.x, a.y), h1 = packh(a.z, a.w);
    u32 h2 = packh(b.x, b.y), h3 = packh(b.z, b.w);
    asm volatile("st.shared.v4.b32 [%0], {%1,%2,%3,%4};"
                 :: "r"(addr), "r"(h0), "r"(h1), "r"(h2), "r"(h3) : "memory");
}
#define CPASYNC(dst, src) \
    asm volatile("cp.async.cg.shared.global [%0], [%1], 16;" :: "r"(dst), "l"(src) : "memory")
#define CPCOMMIT() asm volatile("cp.async.commit_group;" ::: "memory")
#define CPWAIT1()  asm volatile("cp.async.wait_group 1;" ::: "memory")

#define LDSM4(R, A)                                                             \
    asm volatile("ldmatrix.sync.aligned.m8n8.x4.shared.b16 {%0,%1,%2,%3}, [%4];" \
        : "=r"((R)[0]), "=r"((R)[1]), "=r"((R)[2]), "=r"((R)[3]) : "r"(A))

__device__ __forceinline__ void mma16816(float* d, const u32* a, const u32* b) {
    asm volatile(
        "mma.sync.aligned.m16n8k16.row.col.f32.f16.f16.f32 "
        "{%0,%1,%2,%3},{%4,%5,%6,%7},{%8,%9},{%0,%1,%2,%3};"
        : "+f"(d[0]), "+f"(d[1]), "+f"(d[2]), "+f"(d[3])
        : "r"(a[0]), "r"(a[1]), "r"(a[2]), "r"(a[3]), "r"(b[0]), "r"(b[1]));
}

// ---------------- fp32 -> fp16 conversion pass (x only) ----------------
__global__ __launch_bounds__(256)
void cvt16(const float* __restrict__ s, __half* __restrict__ d, size_t n) {
    size_t i = ((size_t)blockIdx.x * 256 + threadIdx.x) * 8;
    if (i >= n) return;
    float4 v0 = *(const float4*)(s + i);
    float4 v1 = *(const float4*)(s + i + 4);
    uint4 o;
    o.x = packh(v0.x, v0.y); o.y = packh(v0.z, v0.w);
    o.z = packh(v1.x, v1.y); o.w = packh(v1.z, v1.w);
    *(uint4*)(d + i) = o;
}

// ---------------- small kernels ----------------
__global__ void reset_kernel() {
    int i = threadIdx.x;
    if (i < NE) { g_counts[i] = 0; g_cursor[i] = 0; g_psum[i] = 0.f; }
    if (i == 0) g_zsum = 0.f;
}

__global__ void router_kernel(const float* __restrict__ x,
                              const float* __restrict__ Wgate) {
    int t = blockIdx.x;
    const float* xr = x + (size_t)t * H;
    float p[NE];
#pragma unroll
    for (int e = 0; e < NE; ++e) p[e] = 0.f;
    for (int c = threadIdx.x; c < H; c += blockDim.x) {
        float xv = xr[c];
#pragma unroll
        for (int e = 0; e < NE; ++e) p[e] += xv * Wgate[e * H + c];
    }
    __shared__ float sm[NE][128];
#pragma unroll
    for (int e = 0; e < NE; ++e) sm[e][threadIdx.x] = p[e];
    __syncthreads();
    for (int s = 64; s > 0; s >>= 1) {
        if (threadIdx.x < s)
#pragma unroll
            for (int e = 0; e < NE; ++e)
                sm[e][threadIdx.x] += sm[e][threadIdx.x + s];
        __syncthreads();
    }
    if (threadIdx.x == 0) {
        float lg[NE];
#pragma unroll
        for (int e = 0; e < NE; ++e) lg[e] = sm[e][0];
        float mx = lg[0];
#pragma unroll
        for (int e = 1; e < NE; ++e) mx = fmaxf(mx, lg[e]);
        float se = 0.f, pr[NE];
#pragma unroll
        for (int e = 0; e < NE; ++e) { pr[e] = expf(lg[e] - mx); se += pr[e]; }
        float inv = 1.f / se;
#pragma unroll
        for (int e = 0; e < NE; ++e) pr[e] *= inv;
        int i0 = 0;
#pragma unroll
        for (int e = 1; e < NE; ++e) if (pr[e] > pr[i0]) i0 = e;
        int i1 = (i0 == 0) ? 1 : 0;
#pragma unroll
        for (int e = 0; e < NE; ++e)
            if (e != i0 && pr[e] > pr[i1]) i1 = e;
        float w0 = pr[i0], w1 = pr[i1];
        float ws = 1.f / (w0 + w1);
        g_topi[2 * t] = i0;     g_topw[2 * t] = w0 * ws;
        g_topi[2 * t + 1] = i1; g_topw[2 * t + 1] = w1 * ws;
        atomicAdd(&g_counts[i0], 1);
        atomicAdd(&g_counts[i1], 1);
#pragma unroll
        for (int e = 0; e < NE; ++e) atomicAdd(&g_psum[e], pr[e]);
        float lse = mx + logf(se);
        atomicAdd(&g_zsum, lse * lse);
    }
}

__global__ void finalize_kernel(float* __restrict__ out, int out_size) {
    if (threadIdx.x == 0 && blockIdx.x == 0) {
        int off = 0;
        for (int e = 0; e < NE; ++e) { g_offsets[e] = off; g_cursor[e] = off; off += g_counts[e]; }
        float aux = 0.f;
        for (int e = 0; e < NE; ++e)
            aux += (g_psum[e] / (float)T) * ((float)g_counts[e] / (float)(T * 2));
        aux *= (float)NE;
        float z = g_zsum / (float)T;
        if (out_size > T * H) out[(size_t)T * H] = 0.02f * aux + 0.001f * z;
    }
}

__global__ void assign_kernel() {
    int t = blockIdx.x * blockDim.x + threadIdx.x;
    if (t >= T) return;
#pragma unroll
    for (int k = 0; k < 2; ++k) {
        int e = g_topi[2 * t + k];
        int s = atomicAdd(&g_cursor[e], 1);
        g_tok[s] = t;
        g_sw[s] = g_topw[2 * t + k];
    }
}

// ---------------- fp16 MMA GEMM; A fp16 cp.async, B fp32->fp16 in-loop ------
// MODE 0: A=hx(gather), B=Wg(fp32) -> g_tmp (raw gate, fp32)
// MODE 1: A=hx(gather), B=Wu(fp32) -> g_hact = silu(g_tmp)*u (fp16)
// MODE 2: A=g_hact,     B=Wd(fp32) -> out[tok] += w * result (atomic fp32)
template <int MODE>
__global__ __launch_bounds__(256, 2)
void gemm_kernel(const __half* __restrict__ Asrc, const float* __restrict__ W32,
                 float* __restrict__ outp) {
    constexpr int KD = (MODE == 2) ? IDIM : H;
    constexpr int KT = KD / BK;

    int e = blockIdx.z;
    int cnt = g_counts[e];
    int m0 = blockIdx.x * BM;
    if (m0 >= cnt) return;
    int base = g_offsets[e];
    int n0 = blockIdx.y * BN;

    extern __shared__ char smem[];
    const __half** aptr = (const __half**)smem;       // 128 row pointers (1 KB)
    u32 tilesA = smem_u32(smem) + 1024;               // 3 x 16KB
    u32 tilesB = tilesA + 3 * ASTG;                   // 2 x 16KB

    int tid = threadIdx.x, lane = tid & 31, wid = tid >> 5;
    int wm = wid & 3, wn = wid >> 2;

    if (tid < 128) {
        int r = m0 + tid;
        int slot = base + ((r < cnt) ? r : (cnt - 1));
        aptr[tid] = (MODE == 2) ? (Asrc + (size_t)slot * IDIM)
                                : (Asrc + (size_t)g_tok[slot] * H);
    }
    __syncthreads();

    const float* wB = W32 + (size_t)e * ((size_t)IDIM * H) + (size_t)n0 * KD;

    // A loader: 4 cp.async chunks per thread
    int lrow = tid >> 1, lch = (tid & 1) * 4;
    const __half* aRow = aptr[lrow] + lch * 8;
    u32 so0 = swoff128(lrow, lch),     so1 = swoff128(lrow, lch + 1);
    u32 so2 = swoff128(lrow, lch + 2), so3 = swoff128(lrow, lch + 3);
#define ISSUE_A(sb, k0) do {                  \
    u32 _s = (sb); int _k = (k0);             \
    CPASYNC(_s + so0, aRow + _k);             \
    CPASYNC(_s + so1, aRow + _k + 8);         \
    CPASYNC(_s + so2, aRow + _k + 16);        \
    CPASYNC(_s + so3, aRow + _k + 24);        \
} while (0)

    // B loader: 32 fp32 per thread per k-tile (half a row), convert -> 4 chunks
    const float* bRow = wB + (size_t)lrow * KD + lch * 8;   // same row/half split
    // (lch*8 elements offset works for fp32 too: chunk c covers k [c*8, c*8+8))

    // prologue: A stages 0,1 via cp.async; B0 direct; B1 into regs
    ISSUE_A(tilesA, 0);
    CPCOMMIT();
    ISSUE_A(tilesA + ASTG, BK);
    CPCOMMIT();

    float4 br[8];
    {
#pragma unroll
        for (int i = 0; i < 8; ++i) br[i] = *(const float4*)(bRow + i * 4);
        cvt_sts(tilesB + so0, br[0], br[1]);
        cvt_sts(tilesB + so1, br[2], br[3]);
        cvt_sts(tilesB + so2, br[4], br[5]);
        cvt_sts(tilesB + so3, br[6], br[7]);
        if (KT > 1) {
#pragma unroll
            for (int i = 0; i < 8; ++i) br[i] = *(const float4*)(bRow + BK + i * 4);
        }
    }

    float acc[2][8][4];
#pragma unroll
    for (int i = 0; i < 2; ++i)
#pragma unroll
        for (int j = 0; j < 8; ++j)
#pragma unroll
            for (int c = 0; c < 4; ++c) acc[i][j][c] = 0.f;

#pragma unroll 1
    for (int kt = 0; kt < KT; ++kt) {
        CPWAIT1();
        __syncthreads();
        if (kt + 2 < KT) ISSUE_A(tilesA + ((kt + 2) % 3) * ASTG, (kt + 2) * BK);
        CPCOMMIT();

        u32 sA = tilesA + (kt % 3) * ASTG;
        u32 sB = tilesB + (kt & 1) * BSTG;
        u32 nB = tilesB + ((kt + 1) & 1) * BSTG;

#pragma unroll
        for (int ks = 0; ks < 4; ++ks) {
            u32 Ah[2][4];
#pragma unroll
            for (int mi = 0; mi < 2; ++mi) {
                int row = wm * 32 + mi * 16 + (lane & 15);
                int ch = ks * 2 + (lane >> 4);
                LDSM4(Ah[mi], sA + swoff128(row, ch));
            }
#pragma unroll
            for (int p = 0; p < 4; ++p) {
                int row = wn * 64 + p * 16 + ((lane >> 4) << 3) + (lane & 7);
                int ch = ks * 2 + ((lane >> 3) & 1);
                u32 Bh[4];
                LDSM4(Bh, sB + swoff128(row, ch));
#pragma unroll
                for (int mi = 0; mi < 2; ++mi) {
                    mma16816(acc[mi][2 * p],     Ah[mi], Bh);
                    mma16816(acc[mi][2 * p + 1], Ah[mi], Bh + 2);
                }
            }
            // mid-tile: STS B(kt+1) after ks0; LDG B(kt+2) after ks1
            if (ks == 0 && kt + 1 < KT) {
                cvt_sts(nB + so0, br[0], br[1]);
                cvt_sts(nB + so1, br[2], br[3]);
                cvt_sts(nB + so2, br[4], br[5]);
                cvt_sts(nB + so3, br[6], br[7]);
            }
            if (ks == 1 && kt + 2 < KT) {
                const float* nb = bRow + (kt + 2) * BK;
#pragma unroll
                for (int i = 0; i < 8; ++i) br[i] = *(const float4*)(nb + i * 4);
            }
        }
    }
#undef ISSUE_A

    // epilogue
    int rA = m0 + wm * 32 + (lane >> 2);
    int cA = n0 + wn * 64 + (lane & 3) * 2;
#pragma unroll
    for (int mi = 0; mi < 2; ++mi) {
#pragma unroll
        for (int ni = 0; ni < 8; ++ni) {
            int col = cA + ni * 8;
#pragma unroll
            for (int h = 0; h < 2; ++h) {
                int r = rA + mi * 16 + h * 8;
                if (r >= cnt) continue;
                float v0 = acc[mi][ni][2 * h], v1 = acc[mi][ni][2 * h + 1];
                int slot = base + r;
                if (MODE == 0) {
                    float2 o; o.x = v0; o.y = v1;
                    *(float2*)(g_tmp + (size_t)slot * IDIM + col) = o;
                } else if (MODE == 1) {
                    float2 g = *(const float2*)(g_tmp + (size_t)slot * IDIM + col);
                    float ax = g.x / (1.f + __expf(-g.x)) * v0;
                    float ay = g.y / (1.f + __expf(-g.y)) * v1;
                    *(u32*)(g_hact + (size_t)slot * IDIM + col) = packh(ax, ay);
                } else {
                    float w = g_sw[slot];
                    float* d = outp + (size_t)g_tok[slot] * H + col;
                    atomicAdd(d, w * v0);
                    atomicAdd(d + 1, w * v1);
                }
            }
        }
    }
}

// ---------------- launch ----------------
extern "C" void kernel_launch(void* const* d_in, const int* in_sizes, int n_in,
                              void* d_out, int out_size) {
    const float* x     = (const float*)d_in[0];
    const float* Wgate = (const float*)d_in[1];
    const float* Wg    = (const float*)d_in[2];
    const float* Wu    = (const float*)d_in[3];
    const float* Wd    = (const float*)d_in[4];
    float* out = (float*)d_out;

    cudaFuncSetAttribute(gemm_kernel<0>, cudaFuncAttributeMaxDynamicSharedMemorySize, SMEMSZ);
    cudaFuncSetAttribute(gemm_kernel<1>, cudaFuncAttributeMaxDynamicSharedMemorySize, SMEMSZ);
    cudaFuncSetAttribute(gemm_kernel<2>, cudaFuncAttributeMaxDynamicSharedMemorySize, SMEMSZ);

    __half *hx, *hact;
    cudaGetSymbolAddress((void**)&hx, g_hx);
    cudaGetSymbolAddress((void**)&hact, g_hact);

    cudaMemsetAsync(out, 0, (size_t)out_size * sizeof(float));
    reset_kernel<<<1, 32>>>();
    router_kernel<<<T, 128>>>(x, Wgate);
    finalize_kernel<<<1, 32>>>(out, out_size);
    assign_kernel<<<(T + 255) / 256, 256>>>();

    // x fp32 -> fp16 (weights are converted inside the GEMMs now)
    cvt16<<<(u32)(((size_t)T * H) / 2048), 256>>>(x, hx, (size_t)T * H);

    dim3 g1(T / BM, IDIM / BN, NE);   // (32, 44, 8)
    gemm_kernel<0><<<g1, 256, SMEMSZ>>>(hx, Wg, out);
    gemm_kernel<1><<<g1, 256, SMEMSZ>>>(hx, Wu, out);

    dim3 g2(T / BM, H / BN, NE);      // (32, 32, 8)
    gemm_kernel<2><<<g2, 256, SMEMSZ>>>(hact, Wd, out);
}

// round 13
// speedup vs baseline: 1.5631x; 1.5631x over previous
#include <cuda_runtime.h>
#include <cuda_fp16.h>
#include <math.h>

typedef unsigned int u32;

#define H 4096
#define IDIM 5632
#define NE 8
#define T 4096
#define NSLOTS (T * 2)
#define BM 128
#define BN 128
#define BK 64
// stage: A 16KB @0 | B 16KB @16384 => 32KB; 3 stages
#define STAGE 32768
#define SMEMSZ (1024 + 3 * STAGE)

// ---------------- scratch (device globals; allocation-free) ----------------
__device__ __half g_hx[(size_t)T * H];
__device__ __half g_hwg[(size_t)NE * IDIM * H];
__device__ __half g_hwu[(size_t)NE * IDIM * H];
__device__ __half g_hwd[(size_t)NE * H * IDIM];
__device__ __half g_hact[(size_t)NSLOTS * IDIM];   // silu(g)*u, fp16
__device__ float  g_tmp[(size_t)NSLOTS * IDIM];    // raw gate values fp32
__device__ int    g_counts[NE];
__device__ int    g_offsets[NE];
__device__ int    g_cursor[NE];
__device__ int    g_topi[T * 2];
__device__ float  g_topw[T * 2];
__device__ int    g_tok[NSLOTS];
__device__ float  g_sw[NSLOTS];
__device__ float  g_psum[NE];
__device__ float  g_zsum;

// ---------------- helpers ----------------
__device__ __forceinline__ u32 smem_u32(const void* p) {
    u32 a;
    asm("{ .reg .u64 t; cvta.to.shared.u64 t, %1; cvt.u32.u64 %0, t; }" : "=r"(a) : "l"(p));
    return a;
}
// fp16 tile [128 rows][64 cols], 128B rows = 8 chunks of 16B, full XOR swizzle
__device__ __forceinline__ u32 swoff128(int row, int ch) {
    return (u32)(row * 128 + ((ch ^ (row & 7)) << 4));
}
__device__ __forceinline__ u32 packh(float lo, float hi) {
    u32 r;
    asm("cvt.rn.f16x2.f32 %0, %1, %2;" : "=r"(r) : "f"(hi), "f"(lo));
    return r;
}
#define CPASYNC(dst, src) \
    asm volatile("cp.async.cg.shared.global [%0], [%1], 16;" :: "r"(dst), "l"(src) : "memory")
#define CPCOMMIT() asm volatile("cp.async.commit_group;" ::: "memory")
#define CPWAIT1()  asm volatile("cp.async.wait_group 1;" ::: "memory")

#define LDSM4(R, A)                                                             \
    asm volatile("ldmatrix.sync.aligned.m8n8.x4.shared.b16 {%0,%1,%2,%3}, [%4];" \
        : "=r"((R)[0]), "=r"((R)[1]), "=r"((R)[2]), "=r"((R)[3]) : "r"(A))

__device__ __forceinline__ void mma16816(float* d, const u32* a, const u32* b) {
    asm volatile(
        "mma.sync.aligned.m16n8k16.row.col.f32.f16.f16.f32 "
        "{%0,%1,%2,%3},{%4,%5,%6,%7},{%8,%9},{%0,%1,%2,%3};"
        : "+f"(d[0]), "+f"(d[1]), "+f"(d[2]), "+f"(d[3])
        : "r"(a[0]), "r"(a[1]), "r"(a[2]), "r"(a[3]), "r"(b[0]), "r"(b[1]));
}

// ---------------- fp32 -> fp16 conversion pass ----------------
__global__ __launch_bounds__(256)
void cvt16(const float* __restrict__ s, __half* __restrict__ d, size_t n) {
    size_t i = ((size_t)blockIdx.x * 256 + threadIdx.x) * 8;
    if (i >= n) return;
    float4 v0 = *(const float4*)(s + i);
    float4 v1 = *(const float4*)(s + i + 4);
    uint4 o;
    o.x = packh(v0.x, v0.y); o.y = packh(v0.z, v0.w);
    o.z = packh(v1.x, v1.y); o.w = packh(v1.z, v1.w);
    *(uint4*)(d + i) = o;
}

// ---------------- small kernels ----------------
__global__ void reset_kernel() {
    int i = threadIdx.x;
    if (i < NE) { g_counts[i] = 0; g_cursor[i] = 0; g_psum[i] = 0.f; }
    if (i == 0) g_zsum = 0.f;
}

__global__ void router_kernel(const float* __restrict__ x,
                              const float* __restrict__ Wgate) {
    int t = blockIdx.x;
    const float* xr = x + (size_t)t * H;
    float p[NE];
#pragma unroll
    for (int e = 0; e < NE; ++e) p[e] = 0.f;
    for (int c = threadIdx.x; c < H; c += blockDim.x) {
        float xv = xr[c];
#pragma unroll
        for (int e = 0; e < NE; ++e) p[e] += xv * Wgate[e * H + c];
    }
    __shared__ float sm[NE][128];
#pragma unroll
    for (int e = 0; e < NE; ++e) sm[e][threadIdx.x] = p[e];
    __syncthreads();
    for (int s = 64; s > 0; s >>= 1) {
        if (threadIdx.x < s)
#pragma unroll
            for (int e = 0; e < NE; ++e)
                sm[e][threadIdx.x] += sm[e][threadIdx.x + s];
        __syncthreads();
    }
    if (threadIdx.x == 0) {
        float lg[NE];
#pragma unroll
        for (int e = 0; e < NE; ++e) lg[e] = sm[e][0];
        float mx = lg[0];
#pragma unroll
        for (int e = 1; e < NE; ++e) mx = fmaxf(mx, lg[e]);
        float se = 0.f, pr[NE];
#pragma unroll
        for (int e = 0; e < NE; ++e) { pr[e] = expf(lg[e] - mx); se += pr[e]; }
        float inv = 1.f / se;
#pragma unroll
        for (int e = 0; e < NE; ++e) pr[e] *= inv;
        int i0 = 0;
#pragma unroll
        for (int e = 1; e < NE; ++e) if (pr[e] > pr[i0]) i0 = e;
        int i1 = (i0 == 0) ? 1 : 0;
#pragma unroll
        for (int e = 0; e < NE; ++e)
            if (e != i0 && pr[e] > pr[i1]) i1 = e;
        float w0 = pr[i0], w1 = pr[i1];
        float ws = 1.f / (w0 + w1);
        g_topi[2 * t] = i0;     g_topw[2 * t] = w0 * ws;
        g_topi[2 * t + 1] = i1; g_topw[2 * t + 1] = w1 * ws;
        atomicAdd(&g_counts[i0], 1);
        atomicAdd(&g_counts[i1], 1);
#pragma unroll
        for (int e = 0; e < NE; ++e) atomicAdd(&g_psum[e], pr[e]);
        float lse = mx + logf(se);
        atomicAdd(&g_zsum, lse * lse);
    }
}

__global__ void finalize_kernel(float* __restrict__ out, int out_size) {
    if (threadIdx.x == 0 && blockIdx.x == 0) {
        int off = 0;
        for (int e = 0; e < NE; ++e) { g_offsets[e] = off; g_cursor[e] = off; off += g_counts[e]; }
        float aux = 0.f;
        for (int e = 0; e < NE; ++e)
            aux += (g_psum[e] / (float)T) * ((float)g_counts[e] / (float)(T * 2));
        aux *= (float)NE;
        float z = g_zsum / (float)T;
        if (out_size > T * H) out[(size_t)T * H] = 0.02f * aux + 0.001f * z;
    }
}

__global__ void assign_kernel() {
    int t = blockIdx.x * blockDim.x + threadIdx.x;
    if (t >= T) return;
#pragma unroll
    for (int k = 0; k < 2; ++k) {
        int e = g_topi[2 * t + k];
        int s = atomicAdd(&g_cursor[e], 1);
        g_tok[s] = t;
        g_sw[s] = g_topw[2 * t + k];
    }
}

// ---------------- fp16 MMA GEMM, cp.async 3-stage (R11-proven) -------------
// MODE 0: A=hx(gather), B=hwg -> g_tmp (raw gate, fp32)
// MODE 1: A=hx(gather), B=hwu -> g_hact = silu(g_tmp)*u (fp16)
// MODE 2: A=g_hact,     B=hwd -> out[tok] += w * result (atomic fp32)
template <int MODE>
__global__ __launch_bounds__(256, 2)
void gemm_kernel(const __half* __restrict__ Asrc, const __half* __restrict__ W,
                 float* __restrict__ outp) {
    constexpr int KD = (MODE == 2) ? IDIM : H;
    constexpr int KT = KD / BK;

    int e = blockIdx.z;
    int cnt = g_counts[e];
    int m0 = blockIdx.x * BM;
    if (m0 >= cnt) return;
    int base = g_offsets[e];
    int n0 = blockIdx.y * BN;

    extern __shared__ char smem[];
    const __half** aptr = (const __half**)smem;   // 128 row pointers (1 KB)
    u32 tiles = smem_u32(smem) + 1024;            // 3 stages x 32 KB

    int tid = threadIdx.x, lane = tid & 31, wid = tid >> 5;
    int wm = wid & 3, wn = wid >> 2;

    if (tid < 128) {
        int r = m0 + tid;
        int slot = base + ((r < cnt) ? r : (cnt - 1));
        aptr[tid] = (MODE == 2) ? (Asrc + (size_t)slot * IDIM)
                                : (Asrc + (size_t)g_tok[slot] * H);
    }
    __syncthreads();

    const __half* wB = W + (size_t)e * ((size_t)IDIM * H) + (size_t)n0 * KD;

    // loader: each thread copies 4 A chunks + 4 B chunks (16B each) per stage
    int lrow = tid >> 1, lch = (tid & 1) * 4;
    const __half* aRow = aptr[lrow] + lch * 8;
    const __half* bRow = wB + (size_t)lrow * KD + lch * 8;
    u32 so0 = swoff128(lrow, lch),     so1 = swoff128(lrow, lch + 1);
    u32 so2 = swoff128(lrow, lch + 2), so3 = swoff128(lrow, lch + 3);

#define ISSUE(sb, k0) do {                                  \
    u32 _s = (sb); int _k = (k0);                           \
    CPASYNC(_s + so0,         aRow + _k);                   \
    CPASYNC(_s + so1,         aRow + _k + 8);               \
    CPASYNC(_s + so2,         aRow + _k + 16);              \
    CPASYNC(_s + so3,         aRow + _k + 24);              \
    CPASYNC(_s + 16384 + so0, bRow + _k);                   \
    CPASYNC(_s + 16384 + so1, bRow + _k + 8);               \
    CPASYNC(_s + 16384 + so2, bRow + _k + 16);              \
    CPASYNC(_s + 16384 + so3, bRow + _k + 24);              \
} while (0)

    // prologue: stages 0 and 1
    ISSUE(tiles, 0);
    CPCOMMIT();
    ISSUE(tiles + STAGE, BK);
    CPCOMMIT();

    float acc[2][8][4];
#pragma unroll
    for (int i = 0; i < 2; ++i)
#pragma unroll
        for (int j = 0; j < 8; ++j)
#pragma unroll
            for (int c = 0; c < 4; ++c) acc[i][j][c] = 0.f;

#pragma unroll 1
    for (int kt = 0; kt < KT; ++kt) {
        CPWAIT1();
        __syncthreads();
        if (kt + 2 < KT) {
            int nslot = (kt + 2) % 3;
            ISSUE(tiles + nslot * STAGE, (kt + 2) * BK);
        }
        CPCOMMIT();

        u32 stage = tiles + (kt % 3) * STAGE;
#pragma unroll
        for (int ks = 0; ks < 4; ++ks) {
            u32 Ah[2][4];
#pragma unroll
            for (int mi = 0; mi < 2; ++mi) {
                int row = wm * 32 + mi * 16 + (lane & 15);
                int ch = ks * 2 + (lane >> 4);
                LDSM4(Ah[mi], stage + swoff128(row, ch));
            }
#pragma unroll
            for (int p = 0; p < 4; ++p) {
                int row = wn * 64 + p * 16 + ((lane >> 4) << 3) + (lane & 7);
                int ch = ks * 2 + ((lane >> 3) & 1);
                u32 Bh[4];
                LDSM4(Bh, stage + 16384 + swoff128(row, ch));
#pragma unroll
                for (int mi = 0; mi < 2; ++mi) {
                    mma16816(acc[mi][2 * p],     Ah[mi], Bh);
                    mma16816(acc[mi][2 * p + 1], Ah[mi], Bh + 2);
                }
            }
        }
    }
#undef ISSUE

    // epilogue
    int rA = m0 + wm * 32 + (lane >> 2);
    int cA = n0 + wn * 64 + (lane & 3) * 2;
#pragma unroll
    for (int mi = 0; mi < 2; ++mi) {
#pragma unroll
        for (int ni = 0; ni < 8; ++ni) {
            int col = cA + ni * 8;
#pragma unroll
            for (int h = 0; h < 2; ++h) {
                int r = rA + mi * 16 + h * 8;
                if (r >= cnt) continue;
                float v0 = acc[mi][ni][2 * h], v1 = acc[mi][ni][2 * h + 1];
                int slot = base + r;
                if (MODE == 0) {
                    float2 o; o.x = v0; o.y = v1;
                    *(float2*)(g_tmp + (size_t)slot * IDIM + col) = o;
                } else if (MODE == 1) {
                    float2 g = *(const float2*)(g_tmp + (size_t)slot * IDIM + col);
                    float ax = g.x / (1.f + __expf(-g.x)) * v0;
                    float ay = g.y / (1.f + __expf(-g.y)) * v1;
                    *(u32*)(g_hact + (size_t)slot * IDIM + col) = packh(ax, ay);
                } else {
                    float w = g_sw[slot];
                    float* d = outp + (size_t)g_tok[slot] * H + col;
                    atomicAdd(d, w * v0);
                    atomicAdd(d + 1, w * v1);
                }
            }
        }
    }
}

// ---------------- launch (fork/join overlap of cvt with GEMMs) -------------
extern "C" void kernel_launch(void* const* d_in, const int* in_sizes, int n_in,
                              void* d_out, int out_size) {
    const float* x     = (const float*)d_in[0];
    const float* Wgate = (const float*)d_in[1];
    const float* Wg    = (const float*)d_in[2];
    const float* Wu    = (const float*)d_in[3];
    const float* Wd    = (const float*)d_in[4];
    float* out = (float*)d_out;

    cudaFuncSetAttribute(gemm_kernel<0>, cudaFuncAttributeMaxDynamicSharedMemorySize, SMEMSZ);
    cudaFuncSetAttribute(gemm_kernel<1>, cudaFuncAttributeMaxDynamicSharedMemorySize, SMEMSZ);
    cudaFuncSetAttribute(gemm_kernel<2>, cudaFuncAttributeMaxDynamicSharedMemorySize, SMEMSZ);

    __half *hx, *hwg, *hwu, *hwd, *hact;
    cudaGetSymbolAddress((void**)&hx, g_hx);
    cudaGetSymbolAddress((void**)&hwg, g_hwg);
    cudaGetSymbolAddress((void**)&hwu, g_hwu);
    cudaGetSymbolAddress((void**)&hwd, g_hwd);
    cudaGetSymbolAddress((void**)&hact, g_hact);

    // one-time host-side resources (no device memory involved)
    static cudaStream_t s1 = 0, s2 = 0;
    static cudaEvent_t evF = 0, evU = 0, evD = 0, evR = 0;
    if (!s1) {
        cudaStreamCreateWithFlags(&s1, cudaStreamNonBlocking);
        cudaStreamCreateWithFlags(&s2, cudaStreamNonBlocking);
        cudaEventCreateWithFlags(&evF, cudaEventDisableTiming);
        cudaEventCreateWithFlags(&evU, cudaEventDisableTiming);
        cudaEventCreateWithFlags(&evD, cudaEventDisableTiming);
        cudaEventCreateWithFlags(&evR, cudaEventDisableTiming);
    }

    const size_t NW = (size_t)NE * IDIM * H;   // = NE*H*IDIM

    // default stream: memset first (finalize writes aux into out afterwards)
    cudaMemsetAsync(out, 0, (size_t)out_size * sizeof(float));
    cudaEventRecord(evF, 0);

    // s1: convert Wu and Wd (needed only by GEMM1 / GEMM2)
    cudaStreamWaitEvent(s1, evF, 0);
    cvt16<<<(u32)(NW / 2048), 256, 0, s1>>>(Wu, hwu, NW);
    cudaEventRecord(evU, s1);
    cvt16<<<(u32)(NW / 2048), 256, 0, s1>>>(Wd, hwd, NW);
    cudaEventRecord(evD, s1);

    // s2: router chain (independent of conversions)
    cudaStreamWaitEvent(s2, evF, 0);
    reset_kernel<<<1, 32, 0, s2>>>();
    router_kernel<<<T, 128, 0, s2>>>(x, Wgate);
    finalize_kernel<<<1, 32, 0, s2>>>(out, out_size);
    assign_kernel<<<(T + 255) / 256, 256, 0, s2>>>();
    cudaEventRecord(evR, s2);

    // default: x + Wg conversions, then the GEMM chain
    cvt16<<<(u32)(((size_t)T * H) / 2048), 256>>>(x, hx, (size_t)T * H);
    cvt16<<<(u32)(NW / 2048), 256>>>(Wg, hwg, NW);
    cudaStreamWaitEvent(0, evR, 0);

    dim3 g1(T / BM, IDIM / BN, NE);   // (32, 44, 8)
    gemm_kernel<0><<<g1, 256, SMEMSZ>>>(hx, hwg, out);
    cudaStreamWaitEvent(0, evU, 0);
    gemm_kernel<1><<<g1, 256, SMEMSZ>>>(hx, hwu, out);
    cudaStreamWaitEvent(0, evD, 0);

    dim3 g2(T / BM, H / BN, NE);      // (32, 32, 8)
    gemm_kernel<2><<<g2, 256, SMEMSZ>>>(hact, hwd, out);
}